// round 1
// baseline (speedup 1.0000x reference)
#include <cuda_runtime.h>
#include <cstdint>

// Problem constants (fixed-shape problem: N_OBJ = N_FLOOR = 8192)
#define NPART   8192
#define NY      16                 // j-splits for the min-distance kernel
#define JCHUNK  (NPART / NY)       // 512 floor particles per j-split
#define BLK     256
#define IPT     2                  // object particles per thread in K1
#define GX      (NPART / (BLK * IPT))   // 16
#define NSTEPS  100

// Scratch (static device globals; no allocation anywhere)
__device__ float g_mpart[NY][NPART];          // partial xy-min-dist^2, per j-split
__device__ unsigned long long g_key;          // packed (contact_step << 32) | d2min_bits

// ---------------------------------------------------------------------------
// K1: m_i = min_j [(ox_i - fx_j)^2 + (oy_i - fy_j)^2]
// Exact-rounding ops (no FMA contraction) to bit-match the JAX reference's
// elementwise-square + sum, so threshold comparisons match exactly.
// grid = (GX, NY), block = BLK. Each y-block handles JCHUNK floor particles.
// Also resets g_key for this replay (stream order guarantees it lands before K2).
// ---------------------------------------------------------------------------
__global__ void __launch_bounds__(BLK) k_mindist(const float* __restrict__ obj,
                                                 const float* __restrict__ flo) {
    __shared__ float2 sf[JCHUNK];
    const int jb = blockIdx.y * JCHUNK;
    for (int t = threadIdx.x; t < JCHUNK; t += BLK) {
        sf[t] = make_float2(flo[3 * (jb + t) + 0], flo[3 * (jb + t) + 1]);
    }
    if (blockIdx.x == 0 && blockIdx.y == 0 && threadIdx.x == 0)
        g_key = 0xFFFFFFFFFFFFFFFFULL;
    __syncthreads();

    const int i0 = blockIdx.x * (BLK * IPT) + threadIdx.x;
    const int i1 = i0 + BLK;
    const float ox0 = obj[3 * i0 + 0], oy0 = obj[3 * i0 + 1];
    const float ox1 = obj[3 * i1 + 0], oy1 = obj[3 * i1 + 1];

    // two accumulators per particle to break the fmin dependency chain
    float m0a = 3.4e38f, m0b = 3.4e38f, m1a = 3.4e38f, m1b = 3.4e38f;

#pragma unroll 8
    for (int j = 0; j < JCHUNK; j += 2) {
        const float2 fa = sf[j];
        const float2 fb = sf[j + 1];
        {
            float dx = __fadd_rn(ox0, -fa.x), dy = __fadd_rn(oy0, -fa.y);
            m0a = fminf(m0a, __fadd_rn(__fmul_rn(dx, dx), __fmul_rn(dy, dy)));
        }
        {
            float dx = __fadd_rn(ox0, -fb.x), dy = __fadd_rn(oy0, -fb.y);
            m0b = fminf(m0b, __fadd_rn(__fmul_rn(dx, dx), __fmul_rn(dy, dy)));
        }
        {
            float dx = __fadd_rn(ox1, -fa.x), dy = __fadd_rn(oy1, -fa.y);
            m1a = fminf(m1a, __fadd_rn(__fmul_rn(dx, dx), __fmul_rn(dy, dy)));
        }
        {
            float dx = __fadd_rn(ox1, -fb.x), dy = __fadd_rn(oy1, -fb.y);
            m1b = fminf(m1b, __fadd_rn(__fmul_rn(dx, dx), __fmul_rn(dy, dy)));
        }
    }
    g_mpart[blockIdx.y][i0] = fminf(m0a, m0b);
    g_mpart[blockIdx.y][i1] = fminf(m1a, m1b);
}

// ---------------------------------------------------------------------------
// K2: per-particle first-contact step under free fall (exact scalar recurrence),
// packed 64-bit atomicMin gives (earliest step, min d2 at that step) at once.
// ---------------------------------------------------------------------------
__global__ void __launch_bounds__(BLK) k_contact(const float* __restrict__ obj) {
    const int i = blockIdx.x * blockDim.x + threadIdx.x;
    float m = g_mpart[0][i];
#pragma unroll
    for (int y = 1; y < NY; y++) m = fminf(m, g_mpart[y][i]);

    const float oz  = obj[3 * i + 2];
    const float gdt = __fmul_rn(-9.8f, 0.01f);     // g * DT, fp32-exact as in ref
    float vz = 0.0f, tz = 0.0f;
    int   kfound = -1;
    float d2f = 0.0f;

    for (int k = 0; k < NSTEPS; k++) {
        vz = __fadd_rn(vz, gdt);                    // v_n = v + g*DT
        tz = __fadd_rn(tz, __fmul_rn(vz, 0.01f));   // t_n = t + v_n*DT
        const float dz = __fadd_rn(oz, tz);
        const float d2 = __fadd_rn(m, __fmul_rn(dz, dz));
        // pen > 0  <=>  sqrt(d2 + 1e-12) < 2R
        if (__fsqrt_rn(__fadd_rn(d2, 1e-12f)) < 0.002f) { kfound = k; d2f = d2; break; }
    }
    if (kfound >= 0) {
        const unsigned long long key =
            ((unsigned long long)(unsigned)kfound << 32) | (unsigned long long)__float_as_uint(d2f);
        atomicMin(&g_key, key);
    }
}

// ---------------------------------------------------------------------------
// K3: outputs. p_first (N x 3 f32) then collision mask (float 0/1, with byte
// fallback if out_size indicates a packed-bool tail).
// ---------------------------------------------------------------------------
__global__ void __launch_bounds__(BLK) k_output(const float* __restrict__ obj,
                                                float* __restrict__ out,
                                                int out_size) {
    const unsigned long long key = g_key;
    const unsigned K = (unsigned)(key >> 32);
    const int i = blockIdx.x * blockDim.x + threadIdx.x;

    const float ox = obj[3 * i + 0];
    const float oy = obj[3 * i + 1];
    const float oz = obj[3 * i + 2];

    bool  inc = false;
    float pz  = oz;

    if (K != 0xFFFFFFFFu) {
        // replay the exact translation recurrence up to contact step K
        const float gdt = __fmul_rn(-9.8f, 0.01f);
        float vz = 0.0f, tz = 0.0f;
        for (unsigned k = 0; k <= K; k++) {
            vz = __fadd_rn(vz, gdt);
            tz = __fadd_rn(tz, __fmul_rn(vz, 0.01f));
        }
        const float d2min   = __uint_as_float((unsigned)(key & 0xFFFFFFFFu));
        const float dminmin = __fsqrt_rn(__fadd_rn(d2min, 1e-12f));
        const float maxpen  = __fadd_rn(0.002f, -dminmin);     // 2R - dmin_min
        const float tzc     = __fadd_rn(tz, maxpen);           // t_c.z

        float m = g_mpart[0][i];
#pragma unroll
        for (int y = 1; y < NY; y++) m = fminf(m, g_mpart[y][i]);

        const float dz = __fadd_rn(oz, tz);                    // contact test at t_n
        const float d2 = __fadd_rn(m, __fmul_rn(dz, dz));
        inc = (__fsqrt_rn(__fadd_rn(d2, 1e-12f)) < 0.002f);
        if (inc) pz = __fadd_rn(oz, tzc);                      // p_c.z at t_c
    }

    out[3 * i + 0] = ox;
    out[3 * i + 1] = oy;
    out[3 * i + 2] = pz;

    if (out_size >= 4 * NPART) {
        // mask stored as output-dtype (float32) 0/1 after the positions
        out[3 * NPART + i] = inc ? 1.0f : 0.0f;
    } else {
        // fallback: packed bool bytes immediately after the 3N floats
        ((unsigned char*)out)[3 * NPART * 4 + i] = inc ? 1 : 0;
    }
}

// ---------------------------------------------------------------------------
extern "C" void kernel_launch(void* const* d_in, const int* in_sizes, int n_in,
                              void* d_out, int out_size) {
    const float* obj = (const float*)d_in[0];   // obj_pc  [8192,3] f32
    const float* flo = (const float*)d_in[1];   // floor_pc[8192,3] f32
    (void)n_in; (void)in_sizes;

    dim3 g1(GX, NY);
    k_mindist<<<g1, BLK>>>(obj, flo);
    k_contact<<<NPART / BLK, BLK>>>(obj);
    k_output<<<NPART / BLK, BLK>>>(obj, (float*)d_out, out_size);
}

// round 3
// speedup vs baseline: 1.0950x; 1.0950x over previous
#include <cuda_runtime.h>
#include <cstdint>

// Problem constants (fixed-shape problem: N_OBJ = N_FLOOR = 8192)
#define NPART   8192
#define NY      16                 // j-splits for the min-distance kernel
#define JCHUNK  (NPART / NY)       // 512 floor particles per j-split
#define BLK     256
#define IPT     2                  // object particles per thread in K1
#define GX      (NPART / (BLK * IPT))   // 16
#define NSTEPS  100

// Scratch (static device globals; no allocation anywhere)
__device__ float g_mpart[NY][NPART];          // partial xy-min-dist^2, per j-split
__device__ unsigned long long g_key;          // packed (contact_step << 32) | d2min_bits

// ---- packed f32x2 helpers (sm_100+) --------------------------------------
typedef unsigned long long u64;

__device__ __forceinline__ u64 pack2(float lo, float hi) {
    u64 r; asm("mov.b64 %0, {%1, %2};" : "=l"(r) : "f"(lo), "f"(hi)); return r;
}
__device__ __forceinline__ void unpack2(u64 v, float& lo, float& hi) {
    asm("mov.b64 {%0, %1}, %2;" : "=f"(lo), "=f"(hi) : "l"(v));
}
__device__ __forceinline__ u64 add2(u64 a, u64 b) {
    u64 r; asm("add.rn.f32x2 %0, %1, %2;" : "=l"(r) : "l"(a), "l"(b)); return r;
}
__device__ __forceinline__ u64 mul2(u64 a, u64 b) {
    u64 r; asm("mul.rn.f32x2 %0, %1, %2;" : "=l"(r) : "l"(a), "l"(b)); return r;
}

// one packed unit: two floor particles vs one object particle
// nfx/nfy hold NEGATED floor coords, so add == exact subtract (same rounding).
__device__ __forceinline__ void pair_min(u64 oxp, u64 oyp, u64 nfx, u64 nfy,
                                         float& me, float& mo) {
    u64 dx = add2(oxp, nfx);
    u64 dy = add2(oyp, nfy);
    u64 d2 = add2(mul2(dx, dx), mul2(dy, dy));
    float lo, hi; unpack2(d2, lo, hi);
    me = fminf(me, lo);
    mo = fminf(mo, hi);
}

// ---------------------------------------------------------------------------
// K1: m_i = min_j [(ox_i - fx_j)^2 + (oy_i - fy_j)^2]
// Packed f32x2 over j-pairs; per-lane arithmetic bit-identical to scalar
// __fadd_rn/__fmul_rn version (so threshold comparisons match the reference
// exactly). grid = (GX, NY), block = BLK.
// Also resets g_key for this replay (stream order puts it before K2).
// ---------------------------------------------------------------------------
__global__ void __launch_bounds__(BLK) k_mindist(const float* __restrict__ obj,
                                                 const float* __restrict__ flo) {
    __shared__ __align__(16) float sfx[JCHUNK];   // negated floor x
    __shared__ __align__(16) float sfy[JCHUNK];   // negated floor y
    const int jb = blockIdx.y * JCHUNK;
    for (int t = threadIdx.x; t < JCHUNK; t += BLK) {
        sfx[t] = -flo[3 * (jb + t) + 0];
        sfy[t] = -flo[3 * (jb + t) + 1];
    }
    if (blockIdx.x == 0 && blockIdx.y == 0 && threadIdx.x == 0)
        g_key = 0xFFFFFFFFFFFFFFFFULL;
    __syncthreads();

    const int i0 = blockIdx.x * (BLK * IPT) + threadIdx.x;
    const int i1 = i0 + BLK;
    const u64 ox0 = pack2(obj[3 * i0 + 0], obj[3 * i0 + 0]);
    const u64 oy0 = pack2(obj[3 * i0 + 1], obj[3 * i0 + 1]);
    const u64 ox1 = pack2(obj[3 * i1 + 0], obj[3 * i1 + 0]);
    const u64 oy1 = pack2(obj[3 * i1 + 1], obj[3 * i1 + 1]);

    const ulonglong2* __restrict__ px = reinterpret_cast<const ulonglong2*>(sfx);
    const ulonglong2* __restrict__ py = reinterpret_cast<const ulonglong2*>(sfy);

    float me0 = 3.4e38f, mo0 = 3.4e38f, me1 = 3.4e38f, mo1 = 3.4e38f;

#pragma unroll 4
    for (int j = 0; j < JCHUNK / 4; j++) {
        const ulonglong2 fx = px[j];   // LDS.128: 4 negated x coords (2 packed units)
        const ulonglong2 fy = py[j];
        pair_min(ox0, oy0, fx.x, fy.x, me0, mo0);
        pair_min(ox0, oy0, fx.y, fy.y, me0, mo0);
        pair_min(ox1, oy1, fx.x, fy.x, me1, mo1);
        pair_min(ox1, oy1, fx.y, fy.y, me1, mo1);
    }
    g_mpart[blockIdx.y][i0] = fminf(me0, mo0);
    g_mpart[blockIdx.y][i1] = fminf(me1, mo1);
}

// ---------------------------------------------------------------------------
// K2: per-particle first-contact step under free fall (exact scalar recurrence),
// packed 64-bit atomicMin gives (earliest step, min d2 at that step) at once.
// ---------------------------------------------------------------------------
__global__ void __launch_bounds__(BLK) k_contact(const float* __restrict__ obj) {
    const int i = blockIdx.x * blockDim.x + threadIdx.x;
    float m = g_mpart[0][i];
#pragma unroll
    for (int y = 1; y < NY; y++) m = fminf(m, g_mpart[y][i]);

    const float oz  = obj[3 * i + 2];
    const float gdt = __fmul_rn(-9.8f, 0.01f);     // g * DT, fp32-exact as in ref
    float vz = 0.0f, tz = 0.0f;
    int   kfound = -1;
    float d2f = 0.0f;

    for (int k = 0; k < NSTEPS; k++) {
        vz = __fadd_rn(vz, gdt);                    // v_n = v + g*DT
        tz = __fadd_rn(tz, __fmul_rn(vz, 0.01f));   // t_n = t + v_n*DT
        const float dz = __fadd_rn(oz, tz);
        const float d2 = __fadd_rn(m, __fmul_rn(dz, dz));
        // pen > 0  <=>  sqrt(d2 + 1e-12) < 2R
        if (__fsqrt_rn(__fadd_rn(d2, 1e-12f)) < 0.002f) { kfound = k; d2f = d2; break; }
    }
    if (kfound >= 0) {
        const unsigned long long key =
            ((unsigned long long)(unsigned)kfound << 32) | (unsigned long long)__float_as_uint(d2f);
        atomicMin(&g_key, key);
    }
}

// ---------------------------------------------------------------------------
// K3: outputs. p_first (N x 3 f32) then collision mask (float 0/1, with byte
// fallback if out_size indicates a packed-bool tail).
// ---------------------------------------------------------------------------
__global__ void __launch_bounds__(BLK) k_output(const float* __restrict__ obj,
                                                float* __restrict__ out,
                                                int out_size) {
    const unsigned long long key = g_key;
    const unsigned K = (unsigned)(key >> 32);
    const int i = blockIdx.x * blockDim.x + threadIdx.x;

    const float ox = obj[3 * i + 0];
    const float oy = obj[3 * i + 1];
    const float oz = obj[3 * i + 2];

    bool  inc = false;
    float pz  = oz;

    if (K != 0xFFFFFFFFu) {
        // replay the exact translation recurrence up to contact step K
        const float gdt = __fmul_rn(-9.8f, 0.01f);
        float vz = 0.0f, tz = 0.0f;
        for (unsigned k = 0; k <= K; k++) {
            vz = __fadd_rn(vz, gdt);
            tz = __fadd_rn(tz, __fmul_rn(vz, 0.01f));
        }
        const float d2min   = __uint_as_float((unsigned)(key & 0xFFFFFFFFu));
        const float dminmin = __fsqrt_rn(__fadd_rn(d2min, 1e-12f));
        const float maxpen  = __fadd_rn(0.002f, -dminmin);     // 2R - dmin_min
        const float tzc     = __fadd_rn(tz, maxpen);           // t_c.z

        float m = g_mpart[0][i];
#pragma unroll
        for (int y = 1; y < NY; y++) m = fminf(m, g_mpart[y][i]);

        const float dz = __fadd_rn(oz, tz);                    // contact test at t_n
        const float d2 = __fadd_rn(m, __fmul_rn(dz, dz));
        inc = (__fsqrt_rn(__fadd_rn(d2, 1e-12f)) < 0.002f);
        if (inc) pz = __fadd_rn(oz, tzc);                      // p_c.z at t_c
    }

    out[3 * i + 0] = ox;
    out[3 * i + 1] = oy;
    out[3 * i + 2] = pz;

    if (out_size >= 4 * NPART) {
        // mask stored as output-dtype (float32) 0/1 after the positions
        out[3 * NPART + i] = inc ? 1.0f : 0.0f;
    } else {
        // fallback: packed bool bytes immediately after the 3N floats
        ((unsigned char*)out)[3 * NPART * 4 + i] = inc ? 1 : 0;
    }
}

// ---------------------------------------------------------------------------
extern "C" void kernel_launch(void* const* d_in, const int* in_sizes, int n_in,
                              void* d_out, int out_size) {
    const float* obj = (const float*)d_in[0];   // obj_pc  [8192,3] f32
    const float* flo = (const float*)d_in[1];   // floor_pc[8192,3] f32
    (void)n_in; (void)in_sizes;

    dim3 g1(GX, NY);
    k_mindist<<<g1, BLK>>>(obj, flo);
    k_contact<<<NPART / BLK, BLK>>>(obj);
    k_output<<<NPART / BLK, BLK>>>(obj, (float*)d_out, out_size);
}